// round 17
// baseline (speedup 1.0000x reference)
#include <cuda_runtime.h>
#include <cuda_fp16.h>
#include <math.h>

#define NN 100000
#define NE 1600000
#define C  128
#define OC 64
#define NG 64
#define FB 1024    // fill blocks
#define SB 512     // edge-backup blocks appended to fill

// ---------------- static device scratch (zero-initialized .bss) --------------
__device__ float g_bufA[(size_t)NN * C];   // z (agg out) / h2 (gemm2 in-place)
__device__ float g_bufB[(size_t)NN * C];   // x backup (fp32 fallback path only)
__device__ long long g_ebak[(size_t)2 * NE];  // edge backup (fp16 path)
__device__ int   g_col[NE];
__device__ int   g_cnt[NN];                // zeroed inline by k_scan each replay
__device__ int   g_rowptr[NN + 1];
__device__ int   g_fillptr[NN];
__device__ float g_dinv[NN];
__device__ int   g_gcnt[NG];               // zeroed inline by k_scan each replay
__device__ int   g_goff[NG + 1];
__device__ int   g_useh;                   // 1: h1 staged as fp16 in edge buffer

__device__ __forceinline__ int detect64(const int* e32) {
    int is64 = 1;
    #pragma unroll
    for (int i = 0; i < 8; i++) if (e32[2 * i + 1] != 0) is64 = 0;
    return is64;
}

// idx 0: histograms + set g_useh (edges pristine here)
__global__ void k_hist_all(const void* ei, const void* bat, int E, int N,
                           int size1) {
    int tid = blockIdx.x * blockDim.x + threadIdx.x;
    int stride = gridDim.x * blockDim.x;
    int is64 = detect64((const int*)ei);
    if (blockIdx.x == 0 && threadIdx.x == 0) {
        // fp16 path needs: int64 edges AND edge-buffer bytes (size1*8) >= N*256
        g_useh = (is64 && (size_t)size1 * 8 >= (size_t)N * 256
                  && E <= NE) ? 1 : 0;
    }
    if (is64) {
        const long long* e = (const long long*)ei;
        for (int i = tid; i < E; i += stride)
            atomicAdd(&g_cnt[(int)e[(size_t)E + i]], 1);
        const long long* b = (const long long*)bat;
        for (int i = tid; i < N; i += stride) atomicAdd(&g_gcnt[(int)b[i]], 1);
    } else {
        const int* e = (const int*)ei;
        for (int i = tid; i < E; i += stride)
            atomicAdd(&g_cnt[e[E + i]], 1);
        const int* b = (const int*)bat;
        for (int i = tid; i < N; i += stride) atomicAdd(&g_gcnt[b[i]], 1);
    }
}

// idx 1: single-block fused scan (R9-proven)
__global__ void k_scan(int n) {
    __shared__ int wsum[32];
    __shared__ int carry_s;
    int tid = threadIdx.x;
    int lane = tid & 31, wid = tid >> 5;
    if (tid == 0) carry_s = 0;
    __syncthreads();

    for (int base = 0; base < n; base += 1024) {
        int i = base + tid;
        int v = (i < n) ? g_cnt[i] : 0;
        int x = v;
        #pragma unroll
        for (int o = 1; o < 32; o <<= 1) {
            int t = __shfl_up_sync(~0u, x, o);
            if (lane >= o) x += t;
        }
        if (lane == 31) wsum[wid] = x;
        __syncthreads();
        if (wid == 0) {
            int s = wsum[lane];
            #pragma unroll
            for (int o = 1; o < 32; o <<= 1) {
                int t = __shfl_up_sync(~0u, s, o);
                if (lane >= o) s += t;
            }
            wsum[lane] = s;
        }
        __syncthreads();
        int carry = carry_s;
        int warpoff = (wid > 0) ? wsum[wid - 1] : 0;
        int excl = carry + warpoff + x - v;
        if (i < n) {
            g_rowptr[i] = excl;
            g_fillptr[i] = excl;
            g_dinv[i] = rsqrtf((float)(v + 1));
            g_cnt[i] = 0;
        }
        __syncthreads();
        if (tid == 1023) carry_s = carry + wsum[31];
        __syncthreads();
    }
    if (tid == 0) {
        g_rowptr[n] = carry_s;
        int s = 0;
        #pragma unroll
        for (int g = 0; g < NG; g++) {
            g_goff[g] = s;
            s += g_gcnt[g];
            g_gcnt[g] = 0;
        }
        g_goff[NG] = s;
    }
}

// idx 2: CSR fill + (extra blocks) edge backup when fp16 path active
__global__ void k_fill(const void* ei, int E) {
    if (blockIdx.x >= FB) {
        if (g_useh) {
            int tid = (blockIdx.x - FB) * 256 + threadIdx.x;
            int stride = SB * 256;
            const long long* e = (const long long*)ei;
            int cnt = 2 * E;
            for (int i = tid; i < cnt; i += stride) g_ebak[i] = e[i];
        }
        return;
    }
    int tid = blockIdx.x * blockDim.x + threadIdx.x;
    int stride = FB * blockDim.x;
    int is64 = detect64((const int*)ei);
    if (is64) {
        const long long* e = (const long long*)ei;
        for (int i = tid; i < E; i += stride) {
            int d = (int)e[(size_t)E + i];
            int s = (int)e[i];
            g_col[atomicAdd(&g_fillptr[d], 1)] = s;
        }
    } else {
        const int* e = (const int*)ei;
        for (int i = tid; i < E; i += stride) {
            int d = e[E + i];
            int s = e[i];
            g_col[atomicAdd(&g_fillptr[d], 1)] = s;
        }
    }
}

// idx 3 (PROFILED): layer-1 aggregation (R9-proven fp32 form).
// z_i = di*(di*u_i + sum_j dj*u_j). Saves x rows to bufB only on the
// fp32-fallback path (fp16 path never modifies xbuf -> no restore needed).
__global__ __launch_bounds__(256) void k_agg1(
    const float* __restrict__ Uin, float* __restrict__ Zout,
    float* __restrict__ save, int n)
{
    int node = (blockIdx.x * blockDim.x + threadIdx.x) >> 5;
    int lane = threadIdx.x & 31;
    if (node >= n) return;

    const float4* U4 = (const float4*)Uin;
    float di = g_dinv[node];
    float4 s4 = U4[(size_t)node * 32 + lane];
    if (!g_useh) ((float4*)save)[(size_t)node * 32 + lane] = s4;
    float4 acc = make_float4(s4.x * di, s4.y * di, s4.z * di, s4.w * di);

    int e = g_rowptr[node];
    int end = g_rowptr[node + 1];

    for (; e + 8 <= end; e += 8) {
        int s[8];
        #pragma unroll
        for (int j = 0; j < 8; j++) s[j] = g_col[e + j];
        float w[8];
        #pragma unroll
        for (int j = 0; j < 8; j++) w[j] = g_dinv[s[j]];
        float4 v[8];
        #pragma unroll
        for (int j = 0; j < 8; j++) v[j] = U4[(size_t)s[j] * 32 + lane];
        #pragma unroll
        for (int j = 0; j < 8; j++) {
            acc.x = fmaf(w[j], v[j].x, acc.x);
            acc.y = fmaf(w[j], v[j].y, acc.y);
            acc.z = fmaf(w[j], v[j].z, acc.z);
            acc.w = fmaf(w[j], v[j].w, acc.w);
        }
    }
    for (; e < end; e++) {
        int s = g_col[e];
        float w = g_dinv[s];
        float4 v = U4[(size_t)s * 32 + lane];
        acc.x = fmaf(w, v.x, acc.x);
        acc.y = fmaf(w, v.y, acc.y);
        acc.z = fmaf(w, v.z, acc.z);
        acc.w = fmaf(w, v.w, acc.w);
    }

    ((float4*)Zout)[(size_t)node * 32 + lane] =
        make_float4(di * acc.x, di * acc.y, di * acc.z, di * acc.w);
}

// GEMM accumulate core (64-row tile, full W in smem, k-paired). In-place safe.
__device__ __forceinline__ void gemm_core(
    const float* __restrict__ Z, const float* __restrict__ W,
    int n, int blk, float acc[8][4], int& tn, int& tm, int& row0)
{
    __shared__ float Ws[C * C];
    __shared__ float Zs[64 * C];
    int tid = threadIdx.x;
    row0 = blk * 64;

    for (int i = tid; i < C * C; i += 256) Ws[i] = W[i];
    for (int i = tid; i < 64 * C; i += 256) {
        int r = row0 + (i >> 7);
        Zs[i] = (r < n) ? Z[(size_t)r * C + (i & 127)] : 0.0f;
    }
    __syncthreads();

    tn = tid & 31;
    tm = tid >> 5;
    #pragma unroll
    for (int r = 0; r < 8; r++)
        #pragma unroll
        for (int c = 0; c < 4; c++) acc[r][c] = 0.0f;

    #pragma unroll 8
    for (int k2 = 0; k2 < C / 2; k2++) {
        float4 wv0 = *(const float4*)&Ws[(2 * k2) * C + tn * 4];
        float4 wv1 = *(const float4*)&Ws[(2 * k2 + 1) * C + tn * 4];
        #pragma unroll
        for (int r = 0; r < 8; r++) {
            float2 z = *(const float2*)&Zs[(tm * 8 + r) * C + 2 * k2];
            acc[r][0] += z.x * wv0.x + z.y * wv1.x;
            acc[r][1] += z.x * wv0.y + z.y * wv1.y;
            acc[r][2] += z.x * wv0.z + z.y * wv1.z;
            acc[r][3] += z.x * wv0.w + z.y * wv1.w;
        }
    }
}

// idx 4: gemm1 -> h1. fp16 path: pack half2 into edge buffer (node*256B rows).
// fallback: fp32 into xbuf (R9 behavior).
__global__ __launch_bounds__(256, 2) void k_gemm1(
    const float* __restrict__ Z, const float* __restrict__ W,
    const float* __restrict__ bias, float* __restrict__ Hf,
    void* __restrict__ Hh, int n)
{
    float acc[8][4];
    int tn, tm, row0;
    gemm_core(Z, W, n, blockIdx.x, acc, tn, tm, row0);

    float4 bv = ((const float4*)bias)[tn];
    int useh = g_useh;
    #pragma unroll
    for (int r = 0; r < 8; r++) {
        int row = row0 + tm * 8 + r;
        if (row < n) {
            float4 o;
            o.x = fmaxf(acc[r][0] + bv.x, 0.f);
            o.y = fmaxf(acc[r][1] + bv.y, 0.f);
            o.z = fmaxf(acc[r][2] + bv.z, 0.f);
            o.w = fmaxf(acc[r][3] + bv.w, 0.f);
            if (useh) {
                __half2 h0 = __floats2half2_rn(o.x, o.y);
                __half2 h1 = __floats2half2_rn(o.z, o.w);
                uint2 p;
                p.x = *(unsigned int*)&h0;
                p.y = *(unsigned int*)&h1;
                ((uint2*)Hh)[(size_t)row * 32 + tn] = p;
            } else {
                *(float4*)&Hf[(size_t)row * C + tn * 4] = o;
            }
        }
    }
}

// idx 5: layer-2 aggregation. fp16 path gathers 256B rows from edge buffer
// (half the sectors/DRAM of fp32); fallback = R9 fp32 from xbuf.
__global__ __launch_bounds__(256) void k_agg2(
    const float* __restrict__ Uf, const void* __restrict__ Uh,
    float* __restrict__ Zout, int n)
{
    int node = (blockIdx.x * blockDim.x + threadIdx.x) >> 5;
    int lane = threadIdx.x & 31;
    if (node >= n) return;

    float di = g_dinv[node];
    float4 acc;
    int e = g_rowptr[node];
    int end = g_rowptr[node + 1];

    if (g_useh) {
        const uint2* H2 = (const uint2*)Uh;
        uint2 su = H2[(size_t)node * 32 + lane];
        float2 f0 = __half22float2(*(__half2*)&su.x);
        float2 f1 = __half22float2(*(__half2*)&su.y);
        acc = make_float4(f0.x * di, f0.y * di, f1.x * di, f1.y * di);

        for (; e + 8 <= end; e += 8) {
            int s[8];
            #pragma unroll
            for (int j = 0; j < 8; j++) s[j] = g_col[e + j];
            float w[8];
            #pragma unroll
            for (int j = 0; j < 8; j++) w[j] = g_dinv[s[j]];
            uint2 u[8];
            #pragma unroll
            for (int j = 0; j < 8; j++) u[j] = H2[(size_t)s[j] * 32 + lane];
            #pragma unroll
            for (int j = 0; j < 8; j++) {
                float2 a = __half22float2(*(__half2*)&u[j].x);
                float2 b = __half22float2(*(__half2*)&u[j].y);
                acc.x = fmaf(w[j], a.x, acc.x);
                acc.y = fmaf(w[j], a.y, acc.y);
                acc.z = fmaf(w[j], b.x, acc.z);
                acc.w = fmaf(w[j], b.y, acc.w);
            }
        }
        for (; e < end; e++) {
            int s = g_col[e];
            float w = g_dinv[s];
            uint2 u = H2[(size_t)s * 32 + lane];
            float2 a = __half22float2(*(__half2*)&u.x);
            float2 b = __half22float2(*(__half2*)&u.y);
            acc.x = fmaf(w, a.x, acc.x);
            acc.y = fmaf(w, a.y, acc.y);
            acc.z = fmaf(w, b.x, acc.z);
            acc.w = fmaf(w, b.y, acc.w);
        }
    } else {
        const float4* U4 = (const float4*)Uf;
        float4 s4 = U4[(size_t)node * 32 + lane];
        acc = make_float4(s4.x * di, s4.y * di, s4.z * di, s4.w * di);

        for (; e + 8 <= end; e += 8) {
            int s[8];
            #pragma unroll
            for (int j = 0; j < 8; j++) s[j] = g_col[e + j];
            float w[8];
            #pragma unroll
            for (int j = 0; j < 8; j++) w[j] = g_dinv[s[j]];
            float4 v[8];
            #pragma unroll
            for (int j = 0; j < 8; j++) v[j] = U4[(size_t)s[j] * 32 + lane];
            #pragma unroll
            for (int j = 0; j < 8; j++) {
                acc.x = fmaf(w[j], v[j].x, acc.x);
                acc.y = fmaf(w[j], v[j].y, acc.y);
                acc.z = fmaf(w[j], v[j].z, acc.z);
                acc.w = fmaf(w[j], v[j].w, acc.w);
            }
        }
        for (; e < end; e++) {
            int s = g_col[e];
            float w = g_dinv[s];
            float4 v = U4[(size_t)s * 32 + lane];
            acc.x = fmaf(w, v.x, acc.x);
            acc.y = fmaf(w, v.y, acc.y);
            acc.z = fmaf(w, v.z, acc.z);
            acc.w = fmaf(w, v.w, acc.w);
        }
    }

    ((float4*)Zout)[(size_t)node * 32 + lane] =
        make_float4(di * acc.x, di * acc.y, di * acc.z, di * acc.w);
}

// idx 6: gemm2 (in-place, fp32) + restore blocks.
// fp16 path: restore edge buffer from g_ebak. fallback: restore xbuf from bufB.
__global__ __launch_bounds__(256, 2) void k_gemm_rest(
    const float* __restrict__ Z, const float* __restrict__ W,
    const float* __restrict__ bias, float* __restrict__ H, int n, int gb,
    float* __restrict__ xdst, const float* __restrict__ xsrc, int n4,
    void* __restrict__ edst, int E, int rb)
{
    if (blockIdx.x >= gb) {
        int tid = (blockIdx.x - gb) * 256 + threadIdx.x;
        int stride = rb * 256;
        if (g_useh) {
            long long* d = (long long*)edst;
            int cnt = 2 * E;
            for (int i = tid; i < cnt; i += stride) d[i] = g_ebak[i];
        } else {
            const float4* s4 = (const float4*)xsrc;
            float4* d4 = (float4*)xdst;
            for (int i = tid; i < n4; i += stride) d4[i] = s4[i];
        }
        return;
    }
    float acc[8][4];
    int tn, tm, row0;
    gemm_core(Z, W, n, blockIdx.x, acc, tn, tm, row0);

    float4 bv = ((const float4*)bias)[tn];
    #pragma unroll
    for (int r = 0; r < 8; r++) {
        int row = row0 + tm * 8 + r;
        if (row < n) {
            float4 o;
            o.x = fmaxf(acc[r][0] + bv.x, 0.f);
            o.y = fmaxf(acc[r][1] + bv.y, 0.f);
            o.z = fmaxf(acc[r][2] + bv.z, 0.f);
            o.w = fmaxf(acc[r][3] + bv.w, 0.f);
            *(float4*)&H[(size_t)row * C + tn * 4] = o;
        }
    }
}

// idx 7: fused mean-pool + linear head, one block per graph
__global__ __launch_bounds__(256) void k_poolhead(
    const float* __restrict__ H, const float* __restrict__ Wl,
    const float* __restrict__ bl, float* __restrict__ out)
{
    __shared__ float4 sh[8][32];
    __shared__ float pooled[C];
    int g = blockIdx.x;
    int rr = threadIdx.x >> 5;
    int c4 = threadIdx.x & 31;
    int s = g_goff[g], e = g_goff[g + 1];
    const float4* H4 = (const float4*)H;
    float4 acc = make_float4(0.f, 0.f, 0.f, 0.f);
    for (int r = s + rr; r < e; r += 8) {
        float4 v = H4[(size_t)r * 32 + c4];
        acc.x += v.x; acc.y += v.y; acc.z += v.z; acc.w += v.w;
    }
    sh[rr][c4] = acc;
    __syncthreads();
    if (rr == 0) {
        #pragma unroll
        for (int j = 1; j < 8; j++) {
            float4 v = sh[j][c4];
            acc.x += v.x; acc.y += v.y; acc.z += v.z; acc.w += v.w;
        }
        float inv = 1.0f / fmaxf((float)(e - s), 1.0f);
        pooled[c4 * 4 + 0] = acc.x * inv;
        pooled[c4 * 4 + 1] = acc.y * inv;
        pooled[c4 * 4 + 2] = acc.z * inv;
        pooled[c4 * 4 + 3] = acc.w * inv;
    }
    __syncthreads();
    if (threadIdx.x < OC) {
        int o = threadIdx.x;
        float a = bl[o];
        #pragma unroll 4
        for (int k = 0; k < C; k++) a += pooled[k] * Wl[k * OC + o];
        out[g * OC + o] = a;
    }
}

// ---------------- launch (8 nodes) -------------------------------------------
extern "C" void kernel_launch(void* const* d_in, const int* in_sizes, int n_in,
                              void* d_out, int out_size) {
    float*       xbuf = (float*)d_in[0];
    void*        ebuf = (void*)d_in[1];           // edge buffer; restored if used
    const void*  bat  = d_in[2];
    const float* W1   = (const float*)d_in[3];
    const float* b1   = (const float*)d_in[4];
    const float* W2   = (const float*)d_in[5];
    const float* b2   = (const float*)d_in[6];
    const float* Wl   = (const float*)d_in[7];
    const float* bl   = (const float*)d_in[8];
    float* out = (float*)d_out;

    int N = in_sizes[0] / C;
    int E = in_sizes[1] / 2;
    int gb = (N + 63) / 64;
    int ab = (N * 32 + 255) / 256;
    int rb = 512;

    k_hist_all <<<1024, 256>>>(ebuf, bat, E, N, in_sizes[1]);        // 0
    k_scan     <<<1, 1024>>>(N);                                     // 1
    k_fill     <<<FB + SB, 256>>>(ebuf, E);                          // 2
    // layer 1: fp32 weighted gather from xbuf (save x only on fallback path)
    k_agg1     <<<ab, 256>>>(xbuf, g_bufA, g_bufB, N);               // 3  <-- profiled
    // gemm1 -> h1 (fp16 into edge buffer, or fp32 into xbuf on fallback)
    k_gemm1    <<<gb, 256>>>(g_bufA, W1, b1, xbuf, ebuf, N);         // 4
    // layer 2: fp16 gather from edge buffer (or fp32 from xbuf)
    k_agg2     <<<ab, 256>>>(xbuf, ebuf, g_bufA, N);                 // 5
    // gemm2 in-place + restore (edges or xbuf)
    k_gemm_rest<<<gb + rb, 256>>>(g_bufA, W2, b2, g_bufA, N, gb,
                                  xbuf, g_bufB, N * 32, ebuf, E, rb); // 6
    k_poolhead <<<NG, 256>>>(g_bufA, Wl, bl, out);                   // 7
}